// round 2
// baseline (speedup 1.0000x reference)
#include <cuda_runtime.h>
#include <math.h>

// Problem constants
#define Bn   64
#define Td   256
#define Tp   1024
#define NB   (Bn * 256)      // 16384 combined (batch, 2*D) width
#define NEGV (-1e9f)

// ---------------- device scratch (no allocation allowed) ----------------
__device__ float g_E1[Td * Tp];                 // exp(pb[:256,:1024])
__device__ float g_E2[Tp * Td];                 // transpose of E1
__device__ float g_Wp1[384 * 128];              // packed [Wkp;Wvp;Wqp]
__device__ float g_bp1[384];
__device__ float g_Wp2[384 * 128];              // packed [Wkd;Wvd;Wqd]
__device__ float g_bp2[384];
__device__ float g_P1[Bn * Tp * 384];           // protein projections (k,v,q)
__device__ float g_P2[Bn * Td * 384];           // smiles projections (k,v,q)
__device__ float g_KV1[Tp * NB];                // [j, b*256 + {ev, e}]
__device__ float g_KV2[Td * NB];
__device__ float g_C1[Td * NB];                 // E1 @ KV1
__device__ float g_C2[Tp * NB];                 // E2 @ KV2
__device__ float g_Y1[Bn * Td * 128];           // sigmoid(q)*num/den
__device__ float g_Y2[Bn * Tp * 128];
__device__ float g_Z1[Bn * Td * 128];           // Y @ Wp^T
__device__ float g_Z2[Bn * Tp * 128];
__device__ unsigned g_ob1[Bn * 128];            // orderable-int max accumulators
__device__ unsigned g_ob2[Bn * 128];

// ---------------- float <-> orderable unsigned ----------------
__device__ __forceinline__ unsigned f2key(float f) {
    unsigned u = __float_as_uint(f);
    return (u & 0x80000000u) ? ~u : (u | 0x80000000u);
}
__device__ __forceinline__ float key2f(unsigned u) {
    unsigned b = (u & 0x80000000u) ? (u ^ 0x80000000u) : ~u;
    return __uint_as_float(b);
}

// ---------------- generic tiled SGEMM: C = A * B (+bias) ----------------
// A: row-major [M,K] lda. B: if TRANSB, B[k][n] = Bp[n*ldb + k] (ldb = K stride),
// else row-major [K,N] ldb. C row-major ldc. All dims multiples of tile sizes.
#define BM 64
#define BN 64
#define BK 16

template <bool TRANSB, bool BIAS>
__global__ __launch_bounds__(256) void sgemm(
    const float* __restrict__ A, const float* __restrict__ Bp,
    const float* __restrict__ bias, float* __restrict__ C,
    int M, int N, int K, int lda, int ldb, int ldc)
{
    __shared__ float As[BK][BM];
    __shared__ float Bs[BK][BN];

    const int tid  = threadIdx.x;
    const int tx   = tid & 15;      // col group (4 cols)
    const int ty   = tid >> 4;      // row group (4 rows)
    const int brow = blockIdx.y * BM;
    const int bcol = blockIdx.x * BN;

    // A tile load mapping: 64 rows x 16 k, float4 along k
    const int arow = tid >> 2;          // 0..63
    const int akq  = (tid & 3) * 4;     // 0,4,8,12
    const float* Aptr = A + (size_t)(brow + arow) * lda + akq;

    // B tile load mapping
    int br, bc;
    const float* Bptr;
    if (TRANSB) { br = tid >> 2; bc = (tid & 3) * 4;   Bptr = Bp + (size_t)(bcol + br) * ldb + bc; }
    else        { br = tid >> 4; bc = (tid & 15) * 4;  Bptr = Bp + (size_t)br * ldb + bcol + bc; }

    float acc[4][4] = {};

    for (int k0 = 0; k0 < K; k0 += BK) {
        float4 av = *(const float4*)(Aptr + k0);
        As[akq + 0][arow] = av.x;
        As[akq + 1][arow] = av.y;
        As[akq + 2][arow] = av.z;
        As[akq + 3][arow] = av.w;
        if (TRANSB) {
            float4 bv = *(const float4*)(Bptr + k0);
            Bs[bc + 0][br] = bv.x;
            Bs[bc + 1][br] = bv.y;
            Bs[bc + 2][br] = bv.z;
            Bs[bc + 3][br] = bv.w;
        } else {
            float4 bv = *(const float4*)(Bptr + (size_t)k0 * ldb);
            *(float4*)&Bs[br][bc] = bv;
        }
        __syncthreads();

        #pragma unroll
        for (int kk = 0; kk < BK; kk++) {
            float4 a = *(const float4*)&As[kk][ty * 4];
            float4 b = *(const float4*)&Bs[kk][tx * 4];
            float ar[4] = {a.x, a.y, a.z, a.w};
            float bb[4] = {b.x, b.y, b.z, b.w};
            #pragma unroll
            for (int r = 0; r < 4; r++)
                #pragma unroll
                for (int c = 0; c < 4; c++)
                    acc[r][c] = fmaf(ar[r], bb[c], acc[r][c]);
        }
        __syncthreads();
    }

    float4 bv4 = {0.f, 0.f, 0.f, 0.f};
    if (BIAS) bv4 = *(const float4*)&bias[bcol + tx * 4];
    #pragma unroll
    for (int r = 0; r < 4; r++) {
        int row = brow + ty * 4 + r;
        float4 v;
        v.x = acc[r][0] + bv4.x;
        v.y = acc[r][1] + bv4.y;
        v.z = acc[r][2] + bv4.z;
        v.w = acc[r][3] + bv4.w;
        *(float4*)&C[(size_t)row * ldc + bcol + tx * 4] = v;
    }
}

// ---------------- small kernels ----------------
__global__ void k_init(unsigned* ob1, unsigned* ob2) {
    int i = blockIdx.x * 256 + threadIdx.x;
    if (i < Bn * 128) {
        unsigned k = f2key(NEGV);
        ob1[i] = k;
        ob2[i] = k;
    }
}

__global__ void k_exp_pb(const float* __restrict__ pb, float* __restrict__ E1, float* __restrict__ E2) {
    int idx = blockIdx.x * 256 + threadIdx.x;   // Td*Tp
    if (idx >= Td * Tp) return;
    int i = idx >> 10, j = idx & 1023;
    float v = expf(pb[i * 1024 + j]);           // pos_bias stride = MAX_LEN = 1024
    E1[idx] = v;
    E2[j * Td + i] = v;
}

__global__ void k_pack(const float* __restrict__ Wk, const float* __restrict__ bk,
                       const float* __restrict__ Wv, const float* __restrict__ bv,
                       const float* __restrict__ Wq, const float* __restrict__ bq,
                       float* __restrict__ Wp, float* __restrict__ bp) {
    int i = blockIdx.x * 256 + threadIdx.x;
    if (i < 384 * 128) {
        int r = i >> 7, c = i & 127;
        const float* s = (r < 128) ? Wk : ((r < 256) ? Wv : Wq);
        Wp[i] = s[(r & 127) * 128 + c];
    }
    if (i < 384) {
        bp[i] = (i < 128) ? bk[i] : ((i < 256) ? bv[i - 128] : bq[i - 256]);
    }
}

__global__ void k_buildKV1(const float* __restrict__ P1, const int* __restrict__ pmask,
                           float* __restrict__ KV1) {
    int idx = blockIdx.x * 256 + threadIdx.x;   // Bn*Tp*128
    if (idx >= Bn * Tp * 128) return;
    int d = idx & 127;
    int j = (idx >> 7) & 1023;
    int b = idx >> 17;
    size_t prow = ((size_t)b * Tp + j) * 384;
    float kp = P1[prow + d];
    float vp = P1[prow + 128 + d];
    float m  = (float)pmask[b * Tp + j];
    float e  = m * expf(kp);
    size_t o = (size_t)j * NB + b * 256 + d;
    KV1[o]       = e * vp;
    KV1[o + 128] = e;
}

__global__ void k_buildKV2(const float* __restrict__ P2, const int* __restrict__ smask,
                           float* __restrict__ KV2) {
    int idx = blockIdx.x * 256 + threadIdx.x;   // Bn*Td*128
    if (idx >= Bn * Td * 128) return;
    int d = idx & 127;
    int q = (idx >> 7) & 255;
    int b = idx >> 15;
    size_t prow = ((size_t)b * Td + q) * 384;
    float kd = P2[prow + d];
    float vd = P2[prow + 128 + d];
    float m  = (float)smask[b * Td + q];
    float e  = m * expf(kd);
    size_t o = (size_t)q * NB + b * 256 + d;
    KV2[o]       = e * vd;
    KV2[o + 128] = e;
}

__global__ void k_y1(const float* __restrict__ C1, const float* __restrict__ P2,
                     float* __restrict__ Y1) {
    int idx = blockIdx.x * 256 + threadIdx.x;   // Bn*Td*128
    if (idx >= Bn * Td * 128) return;
    int d = idx & 127;
    int i = (idx >> 7) & 255;
    int b = idx >> 15;
    size_t co = (size_t)i * NB + b * 256 + d;
    float num = C1[co], den = C1[co + 128];
    float q = P2[((size_t)b * Td + i) * 384 + 256 + d];
    float sg = 1.f / (1.f + expf(-q));
    Y1[((size_t)b * Td + i) * 128 + d] = sg * num / den;
}

__global__ void k_y2(const float* __restrict__ C2, const float* __restrict__ P1,
                     float* __restrict__ Y2) {
    int idx = blockIdx.x * 256 + threadIdx.x;   // Bn*Tp*128
    if (idx >= Bn * Tp * 128) return;
    int d = idx & 127;
    int j = (idx >> 7) & 1023;
    int b = idx >> 17;
    size_t co = (size_t)j * NB + b * 256 + d;
    float num = C2[co], den = C2[co + 128];
    float q = P1[((size_t)b * Tp + j) * 384 + 256 + d];
    float sg = 1.f / (1.f + expf(-q));
    Y2[((size_t)b * Tp + j) * 128 + d] = sg * num / den;
}

__global__ void k_maxred(const float* __restrict__ Z, const int* __restrict__ mask,
                         int seq, int chunk, unsigned* __restrict__ ob) {
    int b = blockIdx.x, s = blockIdx.y, t = threadIdx.x;  // 128 threads
    float lm = -3.0e38f;
    bool any = false;
    int i0 = s * chunk;
    for (int ii = 0; ii < chunk; ii++) {
        int i = i0 + ii;
        if (mask[b * seq + i]) {
            float v = Z[((size_t)b * seq + i) * 128 + t];
            lm = fmaxf(lm, v);
            any = true;
        }
    }
    if (any) atomicMax(&ob[b * 128 + t], f2key(lm));
}

__global__ void k_out(const unsigned* __restrict__ ob1, const unsigned* __restrict__ ob2,
                      const float* __restrict__ bpd, const float* __restrict__ bpp,
                      float* __restrict__ out) {
    int i = blockIdx.x * 256 + threadIdx.x;
    if (i < Bn * 128) {
        int t = i & 127;
        out[i]            = key2f(ob1[i]) + bpd[t];
        out[Bn * 128 + i] = key2f(ob2[i]) + bpp[t];
    }
}

// ---------------- launch ----------------
extern "C" void kernel_launch(void* const* d_in, const int* in_sizes, int n_in,
                              void* d_out, int out_size) {
    const float* smiles  = (const float*)d_in[0];
    const float* protein = (const float*)d_in[1];
    const int*   smask   = (const int*)d_in[2];
    const int*   pmask   = (const int*)d_in[3];
    const float* pb      = (const float*)d_in[4];
    const float* Wqd = (const float*)d_in[5],  *bqd = (const float*)d_in[6];
    const float* Wkp = (const float*)d_in[7],  *bkp = (const float*)d_in[8];
    const float* Wvp = (const float*)d_in[9],  *bvp = (const float*)d_in[10];
    const float* Wqp = (const float*)d_in[11], *bqp = (const float*)d_in[12];
    const float* Wkd = (const float*)d_in[13], *bkd = (const float*)d_in[14];
    const float* Wvd = (const float*)d_in[15], *bvd = (const float*)d_in[16];
    const float* Wpd = (const float*)d_in[17], *bpd = (const float*)d_in[18];
    const float* Wpp = (const float*)d_in[19], *bpp = (const float*)d_in[20];
    float* out = (float*)d_out;

    float *E1, *E2, *Wp1, *bp1, *Wp2, *bp2, *P1, *P2, *KV1, *KV2, *C1, *C2, *Y1, *Y2, *Z1, *Z2;
    unsigned *ob1, *ob2;
    cudaGetSymbolAddress((void**)&E1,  g_E1);
    cudaGetSymbolAddress((void**)&E2,  g_E2);
    cudaGetSymbolAddress((void**)&Wp1, g_Wp1);
    cudaGetSymbolAddress((void**)&bp1, g_bp1);
    cudaGetSymbolAddress((void**)&Wp2, g_Wp2);
    cudaGetSymbolAddress((void**)&bp2, g_bp2);
    cudaGetSymbolAddress((void**)&P1,  g_P1);
    cudaGetSymbolAddress((void**)&P2,  g_P2);
    cudaGetSymbolAddress((void**)&KV1, g_KV1);
    cudaGetSymbolAddress((void**)&KV2, g_KV2);
    cudaGetSymbolAddress((void**)&C1,  g_C1);
    cudaGetSymbolAddress((void**)&C2,  g_C2);
    cudaGetSymbolAddress((void**)&Y1,  g_Y1);
    cudaGetSymbolAddress((void**)&Y2,  g_Y2);
    cudaGetSymbolAddress((void**)&Z1,  g_Z1);
    cudaGetSymbolAddress((void**)&Z2,  g_Z2);
    cudaGetSymbolAddress((void**)&ob1, g_ob1);
    cudaGetSymbolAddress((void**)&ob2, g_ob2);

    // init + batch-independent precompute
    k_init<<<(Bn * 128 + 255) / 256, 256>>>(ob1, ob2);
    k_exp_pb<<<(Td * Tp + 255) / 256, 256>>>(pb, E1, E2);
    k_pack<<<(384 * 128 + 255) / 256, 256>>>(Wkp, bkp, Wvp, bvp, Wqp, bqp, Wp1, bp1);
    k_pack<<<(384 * 128 + 255) / 256, 256>>>(Wkd, bkd, Wvd, bvd, Wqd, bqd, Wp2, bp2);

    // fused projections: [k; v; q]  (X @ Wpack^T + bpack)
    sgemm<true, true><<<dim3(384 / BN, (Bn * Tp) / BM), 256>>>(
        protein, Wp1, bp1, P1, Bn * Tp, 384, 128, 128, 128, 384);
    sgemm<true, true><<<dim3(384 / BN, (Bn * Td) / BM), 256>>>(
        smiles, Wp2, bp2, P2, Bn * Td, 384, 128, 128, 128, 384);

    // build KV matrices (exp + key-mask, interleaved [ev | e] per batch)
    k_buildKV1<<<(Bn * Tp * 128) / 256, 256>>>(P1, pmask, KV1);
    k_buildKV2<<<(Bn * Td * 128) / 256, 256>>>(P2, smask, KV2);

    // main AFT GEMMs: shared-A batched contraction as one big GEMM
    sgemm<false, false><<<dim3(NB / BN, Td / BM), 256>>>(
        E1, KV1, nullptr, C1, Td, NB, Tp, Tp, NB, NB);
    sgemm<false, false><<<dim3(NB / BN, Tp / BM), 256>>>(
        E2, KV2, nullptr, C2, Tp, NB, Td, Td, NB, NB);

    // y = sigmoid(q) * num / den
    k_y1<<<(Bn * Td * 128) / 256, 256>>>(C1, P2, Y1);
    k_y2<<<(Bn * Tp * 128) / 256, 256>>>(C2, P1, Y2);

    // output projections (bias folded in at the very end, after max)
    sgemm<true, false><<<dim3(128 / BN, (Bn * Td) / BM), 256>>>(
        Y1, Wpd, nullptr, Z1, Bn * Td, 128, 128, 128, 128, 128);
    sgemm<true, false><<<dim3(128 / BN, (Bn * Tp) / BM), 256>>>(
        Y2, Wpp, nullptr, Z2, Bn * Tp, 128, 128, 128, 128, 128);

    // masked max over sequence
    k_maxred<<<dim3(Bn, 4), 128>>>(Z1, smask, Td, Td / 4, ob1);
    k_maxred<<<dim3(Bn, 16), 128>>>(Z2, pmask, Tp, Tp / 16, ob2);

    // decode + add output bias
    k_out<<<(Bn * 128 + 255) / 256, 256>>>(ob1, ob2, bpd, bpp, out);
}

// round 3
// speedup vs baseline: 2.1566x; 2.1566x over previous
#include <cuda_runtime.h>
#include <cuda_bf16.h>
#include <math.h>
#include <stdint.h>

// Problem constants
#define Bn   64
#define Td   256
#define Tp   1024
#define NB   (Bn * 256)      // 16384 combined (batch, 2*D) width
#define NEGV (-1e9f)

// ---------------- device scratch (no allocation allowed) ----------------
__device__ float g_E1[Td * Tp];                 // exp(pb[:256,:1024])
__device__ float g_E2[Tp * Td];                 // transpose of E1
__device__ float g_Wp1[384 * 128];              // packed [Wkp;Wvp;Wqp]
__device__ float g_bp1[384];
__device__ float g_Wp2[384 * 128];              // packed [Wkd;Wvd;Wqd]
__device__ float g_bp2[384];
__device__ float g_P1[Bn * Tp * 384];           // protein projections (k,v,q)
__device__ float g_P2[Bn * Td * 384];           // smiles projections (k,v,q)
__device__ float g_KV1t[NB * Tp];               // [b*256 + {ev(d), e(d)+128}][j]
__device__ float g_KV2t[NB * Td];
__device__ float g_C1[Td * NB];                 // E1 @ KV1t^T
__device__ float g_C2[Tp * NB];                 // E2 @ KV2t^T
__device__ float g_Y1[Bn * Td * 128];           // sigmoid(q)*num/den
__device__ float g_Y2[Bn * Tp * 128];
__device__ float g_Z1[Bn * Td * 128];           // Y @ Wp^T
__device__ float g_Z2[Bn * Tp * 128];
__device__ unsigned g_ob1[Bn * 128];            // orderable-int max accumulators
__device__ unsigned g_ob2[Bn * 128];

// ---------------- float <-> orderable unsigned ----------------
__device__ __forceinline__ unsigned f2key(float f) {
    unsigned u = __float_as_uint(f);
    return (u & 0x80000000u) ? ~u : (u | 0x80000000u);
}
__device__ __forceinline__ float key2f(unsigned u) {
    unsigned b = (u & 0x80000000u) ? (u ^ 0x80000000u) : ~u;
    return __uint_as_float(b);
}

// ---------------- bf16x3 tensor-core GEMM ----------------
// C[M,N] = A[M,K] @ B[N,K]^T (+bias), fp32 in/out, bf16-split (hi+lo) compute:
//   a*b ~= ah*bh + ah*bl + al*bh     (err ~2^-17 relative)
// Tile 128x128x32, 256 threads (8 warps as 4(m) x 2(n), warp tile 32x64).
#define LDK 40   // smem row stride in halves (pad for conflict-free frag loads)

__device__ __forceinline__ void mma16816(float* d, const uint32_t* a,
                                         uint32_t b0, uint32_t b1) {
    asm volatile(
        "mma.sync.aligned.m16n8k16.row.col.f32.bf16.bf16.f32 "
        "{%0,%1,%2,%3}, {%4,%5,%6,%7}, {%8,%9}, {%0,%1,%2,%3};"
        : "+f"(d[0]), "+f"(d[1]), "+f"(d[2]), "+f"(d[3])
        : "r"(a[0]), "r"(a[1]), "r"(a[2]), "r"(a[3]), "r"(b0), "r"(b1));
}

__device__ __forceinline__ void splitstore(__nv_bfloat16* sh, __nv_bfloat16* sl,
                                           int off, float4 v) {
    __nv_bfloat16 h0 = __float2bfloat16(v.x);
    __nv_bfloat16 h1 = __float2bfloat16(v.y);
    __nv_bfloat16 h2 = __float2bfloat16(v.z);
    __nv_bfloat16 h3 = __float2bfloat16(v.w);
    __nv_bfloat162 hh0; hh0.x = h0; hh0.y = h1;
    __nv_bfloat162 hh1; hh1.x = h2; hh1.y = h3;
    *(__nv_bfloat162*)(sh + off)     = hh0;
    *(__nv_bfloat162*)(sh + off + 2) = hh1;
    __nv_bfloat162 ll0, ll1;
    ll0.x = __float2bfloat16(v.x - __bfloat162float(h0));
    ll0.y = __float2bfloat16(v.y - __bfloat162float(h1));
    ll1.x = __float2bfloat16(v.z - __bfloat162float(h2));
    ll1.y = __float2bfloat16(v.w - __bfloat162float(h3));
    *(__nv_bfloat162*)(sl + off)     = ll0;
    *(__nv_bfloat162*)(sl + off + 2) = ll1;
}

template <bool BIAS>
__global__ __launch_bounds__(256) void gemm_bf16x3(
    const float* __restrict__ A, const float* __restrict__ B,
    const float* __restrict__ bias, float* __restrict__ C,
    int M, int N, int K, int lda, int ldb, int ldc)
{
    __shared__ __nv_bfloat16 Ash[128 * LDK];
    __shared__ __nv_bfloat16 Asl[128 * LDK];
    __shared__ __nv_bfloat16 Bsh[128 * LDK];
    __shared__ __nv_bfloat16 Bsl[128 * LDK];

    const int tid  = threadIdx.x;
    const int lane = tid & 31;
    const int wid  = tid >> 5;
    const int wm   = (wid >> 1) * 32;
    const int wn   = (wid & 1) * 64;
    const int g    = lane >> 2;
    const int c    = lane & 3;
    const int brow = blockIdx.y * 128;
    const int bcol = blockIdx.x * 128;

    // loader mapping: 1024 float4 per 128x32 tile, 4 per thread
    const int lrow = tid >> 3;          // 0..31 (+32*i)
    const int lc4  = (tid & 7) * 4;     // 0,4,...,28

    const float* Abase = A + (size_t)(brow + lrow) * lda + lc4;
    const float* Bbase = B + (size_t)(bcol + lrow) * ldb + lc4;

    float4 ra[4], rb[4];
    #pragma unroll
    for (int i = 0; i < 4; i++) {
        ra[i] = *(const float4*)(Abase + (size_t)(32 * i) * lda);
        rb[i] = *(const float4*)(Bbase + (size_t)(32 * i) * ldb);
    }

    float acc[2][8][4] = {};

    for (int k0 = 0; k0 < K; k0 += 32) {
        #pragma unroll
        for (int i = 0; i < 4; i++) {
            int off = (lrow + 32 * i) * LDK + lc4;
            splitstore(Ash, Asl, off, ra[i]);
            splitstore(Bsh, Bsl, off, rb[i]);
        }
        __syncthreads();

        if (k0 + 32 < K) {
            #pragma unroll
            for (int i = 0; i < 4; i++) {
                ra[i] = *(const float4*)(Abase + (size_t)(32 * i) * lda + k0 + 32);
                rb[i] = *(const float4*)(Bbase + (size_t)(32 * i) * ldb + k0 + 32);
            }
        }

        #pragma unroll
        for (int ck = 0; ck < 2; ck++) {
            uint32_t ah[2][4], al[2][4];
            #pragma unroll
            for (int mt = 0; mt < 2; mt++) {
                int r0 = (wm + mt * 16 + g) * LDK + ck * 16 + 2 * c;
                ah[mt][0] = *(const uint32_t*)&Ash[r0];
                ah[mt][1] = *(const uint32_t*)&Ash[r0 + 8 * LDK];
                ah[mt][2] = *(const uint32_t*)&Ash[r0 + 8];
                ah[mt][3] = *(const uint32_t*)&Ash[r0 + 8 * LDK + 8];
                al[mt][0] = *(const uint32_t*)&Asl[r0];
                al[mt][1] = *(const uint32_t*)&Asl[r0 + 8 * LDK];
                al[mt][2] = *(const uint32_t*)&Asl[r0 + 8];
                al[mt][3] = *(const uint32_t*)&Asl[r0 + 8 * LDK + 8];
            }
            #pragma unroll
            for (int nt = 0; nt < 8; nt++) {
                int b0 = (wn + nt * 8 + g) * LDK + ck * 16 + 2 * c;
                uint32_t bh0 = *(const uint32_t*)&Bsh[b0];
                uint32_t bh1 = *(const uint32_t*)&Bsh[b0 + 8];
                uint32_t bl0 = *(const uint32_t*)&Bsl[b0];
                uint32_t bl1 = *(const uint32_t*)&Bsl[b0 + 8];
                #pragma unroll
                for (int mt = 0; mt < 2; mt++) {
                    mma16816(acc[mt][nt], ah[mt], bh0, bh1);
                    mma16816(acc[mt][nt], al[mt], bh0, bh1);
                    mma16816(acc[mt][nt], ah[mt], bl0, bl1);
                }
            }
        }
        __syncthreads();
    }

    // epilogue
    #pragma unroll
    for (int mt = 0; mt < 2; mt++) {
        #pragma unroll
        for (int nt = 0; nt < 8; nt++) {
            int row = brow + wm + mt * 16 + g;
            int col = bcol + wn + nt * 8 + 2 * c;
            float bx = 0.f, by = 0.f;
            if (BIAS) { bx = bias[col]; by = bias[col + 1]; }
            float2 v0, v1;
            v0.x = acc[mt][nt][0] + bx;
            v0.y = acc[mt][nt][1] + by;
            v1.x = acc[mt][nt][2] + bx;
            v1.y = acc[mt][nt][3] + by;
            *(float2*)&C[(size_t)row * ldc + col]       = v0;
            *(float2*)&C[(size_t)(row + 8) * ldc + col] = v1;
        }
    }
}

// ---------------- small kernels ----------------
__global__ void k_init(unsigned* ob1, unsigned* ob2) {
    int i = blockIdx.x * 256 + threadIdx.x;
    if (i < Bn * 128) {
        unsigned k = f2key(NEGV);
        ob1[i] = k;
        ob2[i] = k;
    }
}

__global__ void k_exp_pb(const float* __restrict__ pb, float* __restrict__ E1, float* __restrict__ E2) {
    int idx = blockIdx.x * 256 + threadIdx.x;   // Td*Tp
    if (idx >= Td * Tp) return;
    int i = idx >> 10, j = idx & 1023;
    float v = expf(pb[i * 1024 + j]);           // pos_bias stride = MAX_LEN = 1024
    E1[idx] = v;
    E2[j * Td + i] = v;
}

__global__ void k_pack(const float* __restrict__ Wk, const float* __restrict__ bk,
                       const float* __restrict__ Wv, const float* __restrict__ bv,
                       const float* __restrict__ Wq, const float* __restrict__ bq,
                       float* __restrict__ Wp, float* __restrict__ bp) {
    int i = blockIdx.x * 256 + threadIdx.x;
    if (i < 384 * 128) {
        int r = i >> 7, c = i & 127;
        const float* s = (r < 128) ? Wk : ((r < 256) ? Wv : Wq);
        Wp[i] = s[(r & 127) * 128 + c];
    }
    if (i < 384) {
        bp[i] = (i < 128) ? bk[i] : ((i < 256) ? bv[i - 128] : bq[i - 256]);
    }
}

// Build KV transposed: KVt[(b*256 + d)][j] = mask*exp(k)*v ; [(b*256+128+d)][j] = mask*exp(k)
// Block = (b, 32-wide j tile). smem-staged transpose, coalesced both sides.
template <int SEQ>
__global__ __launch_bounds__(256) void k_buildKVt(const float* __restrict__ P,
                                                  const int* __restrict__ mask,
                                                  float* __restrict__ KVt) {
    __shared__ float s_ev[32][129];
    __shared__ float s_e[32][129];
    int b  = blockIdx.x;
    int j0 = blockIdx.y * 32;
    int t  = threadIdx.x;
    #pragma unroll
    for (int i = 0; i < 16; i++) {
        int idx = t + 256 * i;
        int j = idx >> 7, d = idx & 127;
        size_t prow = ((size_t)b * SEQ + j0 + j) * 384;
        float kp = P[prow + d];
        float vp = P[prow + 128 + d];
        float m  = (float)mask[b * SEQ + j0 + j];
        float e  = m * expf(kp);
        s_ev[j][d] = e * vp;
        s_e[j][d]  = e;
    }
    __syncthreads();
    #pragma unroll
    for (int i = 0; i < 16; i++) {
        int idx = t + 256 * i;
        int d = idx >> 5, j = idx & 31;
        KVt[((size_t)(b * 256 + d)) * SEQ + j0 + j]       = s_ev[j][d];
        KVt[((size_t)(b * 256 + 128 + d)) * SEQ + j0 + j] = s_e[j][d];
    }
}

__global__ void k_y1(const float* __restrict__ C1, const float* __restrict__ P2,
                     float* __restrict__ Y1) {
    int idx = blockIdx.x * 256 + threadIdx.x;   // Bn*Td*128
    if (idx >= Bn * Td * 128) return;
    int d = idx & 127;
    int i = (idx >> 7) & 255;
    int b = idx >> 15;
    size_t co = (size_t)i * NB + b * 256 + d;
    float num = C1[co], den = C1[co + 128];
    float q = P2[((size_t)b * Td + i) * 384 + 256 + d];
    float sg = 1.f / (1.f + expf(-q));
    Y1[((size_t)b * Td + i) * 128 + d] = sg * num / den;
}

__global__ void k_y2(const float* __restrict__ C2, const float* __restrict__ P1,
                     float* __restrict__ Y2) {
    int idx = blockIdx.x * 256 + threadIdx.x;   // Bn*Tp*128
    if (idx >= Bn * Tp * 128) return;
    int d = idx & 127;
    int j = (idx >> 7) & 1023;
    int b = idx >> 17;
    size_t co = (size_t)j * NB + b * 256 + d;
    float num = C2[co], den = C2[co + 128];
    float q = P1[((size_t)b * Tp + j) * 384 + 256 + d];
    float sg = 1.f / (1.f + expf(-q));
    Y2[((size_t)b * Tp + j) * 128 + d] = sg * num / den;
}

__global__ void k_maxred(const float* __restrict__ Z, const int* __restrict__ mask,
                         int seq, int chunk, unsigned* __restrict__ ob) {
    int b = blockIdx.x, s = blockIdx.y, t = threadIdx.x;  // 128 threads
    float lm = -3.0e38f;
    bool any = false;
    int i0 = s * chunk;
    for (int ii = 0; ii < chunk; ii++) {
        int i = i0 + ii;
        if (mask[b * seq + i]) {
            float v = Z[((size_t)b * seq + i) * 128 + t];
            lm = fmaxf(lm, v);
            any = true;
        }
    }
    if (any) atomicMax(&ob[b * 128 + t], f2key(lm));
}

__global__ void k_out(const unsigned* __restrict__ ob1, const unsigned* __restrict__ ob2,
                      const float* __restrict__ bpd, const float* __restrict__ bpp,
                      float* __restrict__ out) {
    int i = blockIdx.x * 256 + threadIdx.x;
    if (i < Bn * 128) {
        int t = i & 127;
        out[i]            = key2f(ob1[i]) + bpd[t];
        out[Bn * 128 + i] = key2f(ob2[i]) + bpp[t];
    }
}

// ---------------- launch ----------------
extern "C" void kernel_launch(void* const* d_in, const int* in_sizes, int n_in,
                              void* d_out, int out_size) {
    const float* smiles  = (const float*)d_in[0];
    const float* protein = (const float*)d_in[1];
    const int*   smask   = (const int*)d_in[2];
    const int*   pmask   = (const int*)d_in[3];
    const float* pb      = (const float*)d_in[4];
    const float* Wqd = (const float*)d_in[5],  *bqd = (const float*)d_in[6];
    const float* Wkp = (const float*)d_in[7],  *bkp = (const float*)d_in[8];
    const float* Wvp = (const float*)d_in[9],  *bvp = (const float*)d_in[10];
    const float* Wqp = (const float*)d_in[11], *bqp = (const float*)d_in[12];
    const float* Wkd = (const float*)d_in[13], *bkd = (const float*)d_in[14];
    const float* Wvd = (const float*)d_in[15], *bvd = (const float*)d_in[16];
    const float* Wpd = (const float*)d_in[17], *bpd = (const float*)d_in[18];
    const float* Wpp = (const float*)d_in[19], *bpp = (const float*)d_in[20];
    float* out = (float*)d_out;

    float *E1, *E2, *Wp1, *bp1, *Wp2, *bp2, *P1, *P2, *KV1t, *KV2t, *C1, *C2, *Y1, *Y2, *Z1, *Z2;
    unsigned *ob1, *ob2;
    cudaGetSymbolAddress((void**)&E1,   g_E1);
    cudaGetSymbolAddress((void**)&E2,   g_E2);
    cudaGetSymbolAddress((void**)&Wp1,  g_Wp1);
    cudaGetSymbolAddress((void**)&bp1,  g_bp1);
    cudaGetSymbolAddress((void**)&Wp2,  g_Wp2);
    cudaGetSymbolAddress((void**)&bp2,  g_bp2);
    cudaGetSymbolAddress((void**)&P1,   g_P1);
    cudaGetSymbolAddress((void**)&P2,   g_P2);
    cudaGetSymbolAddress((void**)&KV1t, g_KV1t);
    cudaGetSymbolAddress((void**)&KV2t, g_KV2t);
    cudaGetSymbolAddress((void**)&C1,   g_C1);
    cudaGetSymbolAddress((void**)&C2,   g_C2);
    cudaGetSymbolAddress((void**)&Y1,   g_Y1);
    cudaGetSymbolAddress((void**)&Y2,   g_Y2);
    cudaGetSymbolAddress((void**)&Z1,   g_Z1);
    cudaGetSymbolAddress((void**)&Z2,   g_Z2);
    cudaGetSymbolAddress((void**)&ob1,  g_ob1);
    cudaGetSymbolAddress((void**)&ob2,  g_ob2);

    // init + batch-independent precompute
    k_init<<<(Bn * 128 + 255) / 256, 256>>>(ob1, ob2);
    k_exp_pb<<<(Td * Tp + 255) / 256, 256>>>(pb, E1, E2);
    k_pack<<<(384 * 128 + 255) / 256, 256>>>(Wkp, bkp, Wvp, bvp, Wqp, bqp, Wp1, bp1);
    k_pack<<<(384 * 128 + 255) / 256, 256>>>(Wkd, bkd, Wvd, bvd, Wqd, bqd, Wp2, bp2);

    // fused projections: [k; v; q]  (X @ Wpack^T + bpack)
    gemm_bf16x3<true><<<dim3(3, (Bn * Tp) / 128), 256>>>(
        protein, Wp1, bp1, P1, Bn * Tp, 384, 128, 128, 128, 384);
    gemm_bf16x3<true><<<dim3(3, (Bn * Td) / 128), 256>>>(
        smiles, Wp2, bp2, P2, Bn * Td, 384, 128, 128, 128, 384);

    // build transposed KV matrices (exp + key-mask), [nb][j]
    k_buildKVt<Tp><<<dim3(Bn, Tp / 32), 256>>>(P1, pmask, KV1t);
    k_buildKVt<Td><<<dim3(Bn, Td / 32), 256>>>(P2, smask, KV2t);

    // main AFT GEMMs: shared-A batched contraction as one big GEMM (B transposed)
    gemm_bf16x3<false><<<dim3(NB / 128, Td / 128), 256>>>(
        E1, KV1t, nullptr, C1, Td, NB, Tp, Tp, Tp, NB);
    gemm_bf16x3<false><<<dim3(NB / 128, Tp / 128), 256>>>(
        E2, KV2t, nullptr, C2, Tp, NB, Td, Td, Td, NB);

    // y = sigmoid(q) * num / den
    k_y1<<<(Bn * Td * 128) / 256, 256>>>(C1, P2, Y1);
    k_y2<<<(Bn * Tp * 128) / 256, 256>>>(C2, P1, Y2);

    // output projections (bias folded in at the very end, after max)
    gemm_bf16x3<false><<<dim3(1, (Bn * Td) / 128), 256>>>(
        Y1, Wpd, nullptr, Z1, Bn * Td, 128, 128, 128, 128, 128);
    gemm_bf16x3<false><<<dim3(1, (Bn * Tp) / 128), 256>>>(
        Y2, Wpp, nullptr, Z2, Bn * Tp, 128, 128, 128, 128, 128);

    // masked max over sequence
    k_maxred<<<dim3(Bn, 4), 128>>>(Z1, smask, Td, Td / 4, ob1);
    k_maxred<<<dim3(Bn, 16), 128>>>(Z2, pmask, Tp, Tp / 16, ob2);

    // decode + add output bias
    k_out<<<(Bn * 128 + 255) / 256, 256>>>(ob1, ob2, bpd, bpp, out);
}

// round 4
// speedup vs baseline: 2.3044x; 1.0686x over previous
#include <cuda_runtime.h>
#include <cuda_bf16.h>
#include <math.h>
#include <stdint.h>

// Problem constants
#define Bn   64
#define Td   256
#define Tp   1024
#define NB   (Bn * 256)
#define NEGV (-1e9f)
#define AL   __align__(256)

// ---------------- device scratch ----------------
__device__ AL __nv_bfloat16 g_F1h[Td * Tp];             // exp(pb)-1
__device__ AL __nv_bfloat16 g_F2h[Tp * Td];             // transpose
__device__ AL __nv_bfloat16 g_Xph[Bn * Tp * 128], g_Xpl[Bn * Tp * 128];   // protein hi/lo
__device__ AL __nv_bfloat16 g_Xsh[Bn * Td * 128], g_Xsl[Bn * Td * 128];   // smiles hi/lo
__device__ AL __nv_bfloat16 g_Wp1h[384 * 128], g_Wp1l[384 * 128];
__device__ AL __nv_bfloat16 g_Wp2h[384 * 128], g_Wp2l[384 * 128];
__device__ AL float g_bp1[384], g_bp2[384];
__device__ AL __nv_bfloat16 g_Wodh[128 * 128], g_Wodl[128 * 128];
__device__ AL __nv_bfloat16 g_Woph[128 * 128], g_Wopl[128 * 128];
__device__ AL float g_P1[Bn * Tp * 384];
__device__ AL float g_P2[Bn * Td * 384];
__device__ AL __nv_bfloat16 g_KV1th[NB * Tp], g_KV1tl[NB * Tp];
__device__ AL __nv_bfloat16 g_KV2th[NB * Td], g_KV2tl[NB * Td];
__device__ AL float g_base1[NB], g_base2[NB];
__device__ AL float g_C1[Td * NB];
__device__ AL float g_C2[Tp * NB];
__device__ AL __nv_bfloat16 g_Y1h[Bn * Td * 128], g_Y1l[Bn * Td * 128];
__device__ AL __nv_bfloat16 g_Y2h[Bn * Tp * 128], g_Y2l[Bn * Tp * 128];
__device__ AL float g_Z1[Bn * Td * 128];
__device__ AL float g_Z2[Bn * Tp * 128];
__device__ AL unsigned g_ob1[Bn * 128], g_ob2[Bn * 128];

// ---------------- helpers ----------------
__device__ __forceinline__ unsigned f2key(float f) {
    unsigned u = __float_as_uint(f);
    return (u & 0x80000000u) ? ~u : (u | 0x80000000u);
}
__device__ __forceinline__ float key2f(unsigned u) {
    unsigned b = (u & 0x80000000u) ? (u ^ 0x80000000u) : ~u;
    return __uint_as_float(b);
}
__device__ __forceinline__ void mma16816(float* d, const uint32_t* a,
                                         uint32_t b0, uint32_t b1) {
    asm volatile(
        "mma.sync.aligned.m16n8k16.row.col.f32.bf16.bf16.f32 "
        "{%0,%1,%2,%3}, {%4,%5,%6,%7}, {%8,%9}, {%0,%1,%2,%3};"
        : "+f"(d[0]), "+f"(d[1]), "+f"(d[2]), "+f"(d[3])
        : "r"(a[0]), "r"(a[1]), "r"(a[2]), "r"(a[3]), "r"(b0), "r"(b1));
}
__device__ __forceinline__ void ldsm4(uint32_t* r, const __nv_bfloat16* p) {
    uint32_t a = (uint32_t)__cvta_generic_to_shared(p);
    asm volatile("ldmatrix.sync.aligned.m8n8.x4.shared.b16 {%0,%1,%2,%3}, [%4];"
                 : "=r"(r[0]), "=r"(r[1]), "=r"(r[2]), "=r"(r[3]) : "r"(a));
}

// ---------------- bf16 GEMM with precomputed splits ----------------
// C[M,N] = sum over term pairs A_ta @ B_tb^T (+bias), skipping (ta=1,tb=1).
// A: [M,K] bf16 row-major (lda). B: [N,K] bf16 row-major (ldb). C fp32 (ldc).
// Tile 128x128x32, 256 threads, 8 warps (4m x 2n), warp tile 32x64.
// smem layout: row r (0..127), 16B chunk c (0..3): phys = c ^ ((r>>1)&3).
template <int TA, int TB, bool BIAS>
__global__ __launch_bounds__(256, 1) void gemm_bf(
    const __nv_bfloat16* __restrict__ A0, const __nv_bfloat16* __restrict__ A1,
    const __nv_bfloat16* __restrict__ B0, const __nv_bfloat16* __restrict__ B1,
    const float* __restrict__ bias, float* __restrict__ C,
    int K, int lda, int ldb, int ldc)
{
    __shared__ __nv_bfloat16 SA[TA][128 * 32];
    __shared__ __nv_bfloat16 SB[TB][128 * 32];

    const int tid  = threadIdx.x;
    const int lane = tid & 31;
    const int wid  = tid >> 5;
    const int wm   = (wid >> 1) * 32;
    const int wn   = (wid & 1) * 64;
    const int brow = blockIdx.y * 128;
    const int bcol = blockIdx.x * 128;

    // loader: thread covers rows lr, lr+64 at chunk lc
    const int lr  = tid >> 2;
    const int lc  = tid & 3;
    const int so0 = lr * 32 + ((lc ^ ((lr >> 1) & 3)) * 8);
    const int so1 = (lr + 64) * 32 + ((lc ^ (((lr + 64) >> 1) & 3)) * 8);

    const __nv_bfloat16* gA0 = A0 + (size_t)(brow + lr) * lda + lc * 8;
    const __nv_bfloat16* gA1 = (TA > 1) ? (A1 + (size_t)(brow + lr) * lda + lc * 8) : A0;
    const __nv_bfloat16* gB0 = B0 + (size_t)(bcol + lr) * ldb + lc * 8;
    const __nv_bfloat16* gB1 = (TB > 1) ? (B1 + (size_t)(bcol + lr) * ldb + lc * 8) : B0;
    const size_t a64 = (size_t)64 * lda, b64 = (size_t)64 * ldb;

    uint4 ra0[2], ra1[2], rb0[2], rb1[2];
    ra0[0] = *(const uint4*)(gA0); ra0[1] = *(const uint4*)(gA0 + a64);
    if (TA > 1) { ra1[0] = *(const uint4*)(gA1); ra1[1] = *(const uint4*)(gA1 + a64); }
    rb0[0] = *(const uint4*)(gB0); rb0[1] = *(const uint4*)(gB0 + b64);
    if (TB > 1) { rb1[0] = *(const uint4*)(gB1); rb1[1] = *(const uint4*)(gB1 + b64); }

    float acc[2][8][4] = {};

    // ldmatrix per-lane bases
    const int arow_b = (lane & 7) + ((lane >> 3) & 1) * 8;  // + wm + mt*16
    const int achk_b = (lane >> 4);                          // + 2*ck
    const int brow_b = (lane & 7) + (lane >> 4) * 8;         // + wn + ntp*16
    const int bchk_b = (lane >> 3) & 1;                      // + 2*ck

    for (int k0 = 0; k0 < K; k0 += 32) {
        *(uint4*)&SA[0][so0] = ra0[0]; *(uint4*)&SA[0][so1] = ra0[1];
        if (TA > 1) { *(uint4*)&SA[1][so0] = ra1[0]; *(uint4*)&SA[1][so1] = ra1[1]; }
        *(uint4*)&SB[0][so0] = rb0[0]; *(uint4*)&SB[0][so1] = rb0[1];
        if (TB > 1) { *(uint4*)&SB[1][so0] = rb1[0]; *(uint4*)&SB[1][so1] = rb1[1]; }
        __syncthreads();

        if (k0 + 32 < K) {
            ra0[0] = *(const uint4*)(gA0 + k0 + 32);
            ra0[1] = *(const uint4*)(gA0 + a64 + k0 + 32);
            if (TA > 1) {
                ra1[0] = *(const uint4*)(gA1 + k0 + 32);
                ra1[1] = *(const uint4*)(gA1 + a64 + k0 + 32);
            }
            rb0[0] = *(const uint4*)(gB0 + k0 + 32);
            rb0[1] = *(const uint4*)(gB0 + b64 + k0 + 32);
            if (TB > 1) {
                rb1[0] = *(const uint4*)(gB1 + k0 + 32);
                rb1[1] = *(const uint4*)(gB1 + b64 + k0 + 32);
            }
        }

        #pragma unroll
        for (int ck = 0; ck < 2; ck++) {
            uint32_t af[TA][2][4];
            #pragma unroll
            for (int mt = 0; mt < 2; mt++) {
                int row = wm + mt * 16 + arow_b;
                int chk = 2 * ck + achk_b;
                int off = row * 32 + ((chk ^ ((row >> 1) & 3)) * 8);
                ldsm4(af[0][mt], &SA[0][off]);
                if (TA > 1) ldsm4(af[TA - 1][mt], &SA[TA - 1][off]);
            }
            #pragma unroll
            for (int ntp = 0; ntp < 4; ntp++) {
                int row = wn + ntp * 16 + brow_b;
                int chk = 2 * ck + bchk_b;
                int off = row * 32 + ((chk ^ ((row >> 1) & 3)) * 8);
                uint32_t bf0[4], bf1[4];
                ldsm4(bf0, &SB[0][off]);
                if (TB > 1) ldsm4(bf1, &SB[TB - 1][off]);
                #pragma unroll
                for (int mt = 0; mt < 2; mt++) {
                    mma16816(acc[mt][2 * ntp],     af[0][mt], bf0[0], bf0[1]);
                    mma16816(acc[mt][2 * ntp + 1], af[0][mt], bf0[2], bf0[3]);
                    if (TB > 1) {
                        mma16816(acc[mt][2 * ntp],     af[0][mt], bf1[0], bf1[1]);
                        mma16816(acc[mt][2 * ntp + 1], af[0][mt], bf1[2], bf1[3]);
                    }
                    if (TA > 1) {
                        mma16816(acc[mt][2 * ntp],     af[TA - 1][mt], bf0[0], bf0[1]);
                        mma16816(acc[mt][2 * ntp + 1], af[TA - 1][mt], bf0[2], bf0[3]);
                    }
                }
            }
        }
        __syncthreads();
    }

    const int g = lane >> 2;
    const int c = lane & 3;
    #pragma unroll
    for (int mt = 0; mt < 2; mt++) {
        #pragma unroll
        for (int nt = 0; nt < 8; nt++) {
            int row = brow + wm + mt * 16 + g;
            int col = bcol + wn + nt * 8 + 2 * c;
            float bx = 0.f, by = 0.f;
            if (BIAS) { bx = bias[col]; by = bias[col + 1]; }
            float2 v0, v1;
            v0.x = acc[mt][nt][0] + bx;
            v0.y = acc[mt][nt][1] + by;
            v1.x = acc[mt][nt][2] + bx;
            v1.y = acc[mt][nt][3] + by;
            *(float2*)&C[(size_t)row * ldc + col]       = v0;
            *(float2*)&C[(size_t)(row + 8) * ldc + col] = v1;
        }
    }
}

// ---------------- small kernels ----------------
__global__ void k_init(unsigned* ob1, unsigned* ob2, float* base1, float* base2) {
    int i = blockIdx.x * 256 + threadIdx.x;
    if (i < Bn * 128) {
        unsigned k = f2key(NEGV);
        ob1[i] = k; ob2[i] = k;
    }
    if (i < NB) { base1[i] = 0.f; base2[i] = 0.f; }
}

// F = exp(pb)-1, plus transpose (smem tiled)
__global__ void k_expf(const float* __restrict__ pb, __nv_bfloat16* __restrict__ F1,
                       __nv_bfloat16* __restrict__ F2) {
    __shared__ float s[32][33];
    int j0 = blockIdx.x * 32, i0 = blockIdx.y * 32;
    int tx = threadIdx.x & 31, ty = threadIdx.x >> 5;
    #pragma unroll
    for (int r = ty; r < 32; r += 8) {
        float v = expf(pb[(i0 + r) * 1024 + j0 + tx]) - 1.0f;
        F1[(i0 + r) * Tp + j0 + tx] = __float2bfloat16(v);
        s[r][tx] = v;
    }
    __syncthreads();
    #pragma unroll
    for (int r = ty; r < 32; r += 8)
        F2[(j0 + r) * Td + i0 + tx] = __float2bfloat16(s[tx][r]);
}

// fp32 -> (hi, lo) bf16 split, float4-vectorized
__global__ void k_split(const float* __restrict__ x, __nv_bfloat16* __restrict__ h,
                        __nv_bfloat16* __restrict__ l, int n4) {
    int i = blockIdx.x * 256 + threadIdx.x;
    if (i >= n4) return;
    float4 v = ((const float4*)x)[i];
    __nv_bfloat16 h0 = __float2bfloat16(v.x), h1 = __float2bfloat16(v.y);
    __nv_bfloat16 h2 = __float2bfloat16(v.z), h3 = __float2bfloat16(v.w);
    __nv_bfloat162 hh0, hh1, ll0, ll1;
    hh0.x = h0; hh0.y = h1; hh1.x = h2; hh1.y = h3;
    ll0.x = __float2bfloat16(v.x - __bfloat162float(h0));
    ll0.y = __float2bfloat16(v.y - __bfloat162float(h1));
    ll1.x = __float2bfloat16(v.z - __bfloat162float(h2));
    ll1.y = __float2bfloat16(v.w - __bfloat162float(h3));
    ((__nv_bfloat162*)h)[2 * i]     = hh0;
    ((__nv_bfloat162*)h)[2 * i + 1] = hh1;
    ((__nv_bfloat162*)l)[2 * i]     = ll0;
    ((__nv_bfloat162*)l)[2 * i + 1] = ll1;
}

__global__ void k_pack_split(const float* __restrict__ Wk, const float* __restrict__ bk,
                             const float* __restrict__ Wv, const float* __restrict__ bv,
                             const float* __restrict__ Wq, const float* __restrict__ bq,
                             __nv_bfloat16* __restrict__ Wh, __nv_bfloat16* __restrict__ Wl,
                             float* __restrict__ bp) {
    int i = blockIdx.x * 256 + threadIdx.x;
    if (i < 384 * 128) {
        int r = i >> 7, c = i & 127;
        const float* s = (r < 128) ? Wk : ((r < 256) ? Wv : Wq);
        float w = s[(r & 127) * 128 + c];
        __nv_bfloat16 h = __float2bfloat16(w);
        Wh[i] = h;
        Wl[i] = __float2bfloat16(w - __bfloat162float(h));
    }
    if (i < 384) bp[i] = (i < 128) ? bk[i] : ((i < 256) ? bv[i - 128] : bq[i - 256]);
}

// Build KV transposed bf16 hi/lo + exact fp32 column sums (base)
template <int SEQ>
__global__ __launch_bounds__(256) void k_buildKVt(const float* __restrict__ P,
        const int* __restrict__ mask, __nv_bfloat16* __restrict__ KVh,
        __nv_bfloat16* __restrict__ KVl, float* __restrict__ base) {
    __shared__ float s_ev[32][129];
    __shared__ float s_e[32][129];
    int b = blockIdx.x, j0 = blockIdx.y * 32, t = threadIdx.x;
    #pragma unroll
    for (int i = 0; i < 16; i++) {
        int idx = t + 256 * i;
        int j = idx >> 7, d = idx & 127;
        size_t prow = ((size_t)b * SEQ + j0 + j) * 384;
        float kp = P[prow + d];
        float vp = P[prow + 128 + d];
        float m  = (float)mask[b * SEQ + j0 + j];
        float e  = m * expf(kp);
        s_ev[j][d] = e * vp;
        s_e[j][d]  = e;
    }
    __syncthreads();
    {
        float s = 0.f;
        if (t < 128) { for (int j = 0; j < 32; j++) s += s_ev[j][t]; }
        else         { for (int j = 0; j < 32; j++) s += s_e[j][t - 128]; }
        atomicAdd(&base[b * 256 + t], s);
    }
    #pragma unroll
    for (int i = 0; i < 16; i++) {
        int idx = t + 256 * i;
        int d = idx >> 5, j = idx & 31;
        float v1 = s_ev[j][d], v2 = s_e[j][d];
        size_t o1 = ((size_t)(b * 256 + d)) * SEQ + j0 + j;
        size_t o2 = ((size_t)(b * 256 + 128 + d)) * SEQ + j0 + j;
        __nv_bfloat16 h1 = __float2bfloat16(v1), h2 = __float2bfloat16(v2);
        KVh[o1] = h1; KVl[o1] = __float2bfloat16(v1 - __bfloat162float(h1));
        KVh[o2] = h2; KVl[o2] = __float2bfloat16(v2 - __bfloat162float(h2));
    }
}

__global__ void k_y1(const float* __restrict__ C1, const float* __restrict__ base1,
                     const float* __restrict__ P2,
                     __nv_bfloat16* __restrict__ Yh, __nv_bfloat16* __restrict__ Yl) {
    int idx = blockIdx.x * 256 + threadIdx.x;
    if (idx >= Bn * Td * 128) return;
    int d = idx & 127, i = (idx >> 7) & 255, b = idx >> 15;
    size_t co = (size_t)i * NB + b * 256 + d;
    float num = C1[co] + base1[b * 256 + d];
    float den = C1[co + 128] + base1[b * 256 + 128 + d];
    float q = P2[((size_t)b * Td + i) * 384 + 256 + d];
    float sg = 1.f / (1.f + expf(-q));
    float y = sg * num / den;
    __nv_bfloat16 h = __float2bfloat16(y);
    size_t o = ((size_t)b * Td + i) * 128 + d;
    Yh[o] = h;
    Yl[o] = __float2bfloat16(y - __bfloat162float(h));
}

__global__ void k_y2(const float* __restrict__ C2, const float* __restrict__ base2,
                     const float* __restrict__ P1,
                     __nv_bfloat16* __restrict__ Yh, __nv_bfloat16* __restrict__ Yl) {
    int idx = blockIdx.x * 256 + threadIdx.x;
    if (idx >= Bn * Tp * 128) return;
    int d = idx & 127, j = (idx >> 7) & 1023, b = idx >> 17;
    size_t co = (size_t)j * NB + b * 256 + d;
    float num = C2[co] + base2[b * 256 + d];
    float den = C2[co + 128] + base2[b * 256 + 128 + d];
    float q = P1[((size_t)b * Tp + j) * 384 + 256 + d];
    float sg = 1.f / (1.f + expf(-q));
    float y = sg * num / den;
    __nv_bfloat16 h = __float2bfloat16(y);
    size_t o = ((size_t)b * Tp + j) * 128 + d;
    Yh[o] = h;
    Yl[o] = __float2bfloat16(y - __bfloat162float(h));
}

__global__ void k_maxred(const float* __restrict__ Z, const int* __restrict__ mask,
                         int seq, int chunk, unsigned* __restrict__ ob) {
    int b = blockIdx.x, s = blockIdx.y, t = threadIdx.x;
    float lm = -3.0e38f;
    bool any = false;
    int i0 = s * chunk;
    for (int ii = 0; ii < chunk; ii++) {
        int i = i0 + ii;
        if (mask[b * seq + i]) {
            float v = Z[((size_t)b * seq + i) * 128 + t];
            lm = fmaxf(lm, v);
            any = true;
        }
    }
    if (any) atomicMax(&ob[b * 128 + t], f2key(lm));
}

__global__ void k_out(const unsigned* __restrict__ ob1, const unsigned* __restrict__ ob2,
                      const float* __restrict__ bpd, const float* __restrict__ bpp,
                      float* __restrict__ out) {
    int i = blockIdx.x * 256 + threadIdx.x;
    if (i < Bn * 128) {
        int t = i & 127;
        out[i]            = key2f(ob1[i]) + bpd[t];
        out[Bn * 128 + i] = key2f(ob2[i]) + bpp[t];
    }
}

// ---------------- launch ----------------
#define SYM(p, s) cudaGetSymbolAddress((void**)&p, s)

extern "C" void kernel_launch(void* const* d_in, const int* in_sizes, int n_in,
                              void* d_out, int out_size) {
    const float* smiles  = (const float*)d_in[0];
    const float* protein = (const float*)d_in[1];
    const int*   smask   = (const int*)d_in[2];
    const int*   pmask   = (const int*)d_in[3];
    const float* pb      = (const float*)d_in[4];
    const float* Wqd = (const float*)d_in[5],  *bqd = (const float*)d_in[6];
    const float* Wkp = (const float*)d_in[7],  *bkp = (const float*)d_in[8];
    const float* Wvp = (const float*)d_in[9],  *bvp = (const float*)d_in[10];
    const float* Wqp = (const float*)d_in[11], *bqp = (const float*)d_in[12];
    const float* Wkd = (const float*)d_in[13], *bkd = (const float*)d_in[14];
    const float* Wvd = (const float*)d_in[15], *bvd = (const float*)d_in[16];
    const float* Wpd = (const float*)d_in[17], *bpd = (const float*)d_in[18];
    const float* Wpp = (const float*)d_in[19], *bpp = (const float*)d_in[20];
    float* out = (float*)d_out;

    __nv_bfloat16 *F1h, *F2h, *Xph, *Xpl, *Xsh, *Xsl, *Wp1h, *Wp1l, *Wp2h, *Wp2l;
    __nv_bfloat16 *Wodh, *Wodl, *Woph, *Wopl, *KV1th, *KV1tl, *KV2th, *KV2tl;
    __nv_bfloat16 *Y1h, *Y1l, *Y2h, *Y2l;
    float *bp1, *bp2, *P1, *P2, *base1, *base2, *C1, *C2, *Z1, *Z2;
    unsigned *ob1, *ob2;
    SYM(F1h, g_F1h);   SYM(F2h, g_F2h);
    SYM(Xph, g_Xph);   SYM(Xpl, g_Xpl);   SYM(Xsh, g_Xsh);   SYM(Xsl, g_Xsl);
    SYM(Wp1h, g_Wp1h); SYM(Wp1l, g_Wp1l); SYM(Wp2h, g_Wp2h); SYM(Wp2l, g_Wp2l);
    SYM(bp1, g_bp1);   SYM(bp2, g_bp2);
    SYM(Wodh, g_Wodh); SYM(Wodl, g_Wodl); SYM(Woph, g_Woph); SYM(Wopl, g_Wopl);
    SYM(P1, g_P1);     SYM(P2, g_P2);
    SYM(KV1th, g_KV1th); SYM(KV1tl, g_KV1tl); SYM(KV2th, g_KV2th); SYM(KV2tl, g_KV2tl);
    SYM(base1, g_base1); SYM(base2, g_base2);
    SYM(C1, g_C1);     SYM(C2, g_C2);
    SYM(Y1h, g_Y1h);   SYM(Y1l, g_Y1l);   SYM(Y2h, g_Y2h);   SYM(Y2l, g_Y2l);
    SYM(Z1, g_Z1);     SYM(Z2, g_Z2);
    SYM(ob1, g_ob1);   SYM(ob2, g_ob2);

    // init + batch-independent precompute
    k_init<<<NB / 256, 256>>>(ob1, ob2, base1, base2);
    k_expf<<<dim3(Tp / 32, Td / 32), 256>>>(pb, F1h, F2h);
    k_split<<<(Bn * Tp * 128 / 4 + 255) / 256, 256>>>(protein, Xph, Xpl, Bn * Tp * 128 / 4);
    k_split<<<(Bn * Td * 128 / 4 + 255) / 256, 256>>>(smiles, Xsh, Xsl, Bn * Td * 128 / 4);
    k_split<<<(128 * 128 / 4 + 255) / 256, 256>>>(Wpd, Wodh, Wodl, 128 * 128 / 4);
    k_split<<<(128 * 128 / 4 + 255) / 256, 256>>>(Wpp, Woph, Wopl, 128 * 128 / 4);
    k_pack_split<<<192, 256>>>(Wkp, bkp, Wvp, bvp, Wqp, bqp, Wp1h, Wp1l, bp1);
    k_pack_split<<<192, 256>>>(Wkd, bkd, Wvd, bvd, Wqd, bqd, Wp2h, Wp2l, bp2);

    // fused projections: [k; v; q]
    gemm_bf<2, 2, true><<<dim3(3, (Bn * Tp) / 128), 256>>>(
        Xph, Xpl, Wp1h, Wp1l, bp1, P1, 128, 128, 128, 384);
    gemm_bf<2, 2, true><<<dim3(3, (Bn * Td) / 128), 256>>>(
        Xsh, Xsl, Wp2h, Wp2l, bp2, P2, 128, 128, 128, 384);

    // build transposed KV (bf16 hi/lo) + exact column-sum base
    k_buildKVt<Tp><<<dim3(Bn, Tp / 32), 256>>>(P1, pmask, KV1th, KV1tl, base1);
    k_buildKVt<Td><<<dim3(Bn, Td / 32), 256>>>(P2, smask, KV2th, KV2tl, base2);

    // main AFT GEMMs: C = F @ KV (base added in k_y)
    gemm_bf<1, 2, false><<<dim3(NB / 128, Td / 128), 256>>>(
        F1h, nullptr, KV1th, KV1tl, nullptr, C1, Tp, Tp, Tp, NB);
    gemm_bf<1, 2, false><<<dim3(NB / 128, Tp / 128), 256>>>(
        F2h, nullptr, KV2th, KV2tl, nullptr, C2, Td, Td, Td, NB);

    // y = sigmoid(q) * num / den  (split to bf16 hi/lo for epilogue GEMM)
    k_y1<<<(Bn * Td * 128) / 256, 256>>>(C1, base1, P2, Y1h, Y1l);
    k_y2<<<(Bn * Tp * 128) / 256, 256>>>(C2, base2, P1, Y2h, Y2l);

    // output projections
    gemm_bf<2, 2, false><<<dim3(1, (Bn * Td) / 128), 256>>>(
        Y1h, Y1l, Wodh, Wodl, nullptr, Z1, 128, 128, 128, 128);
    gemm_bf<2, 2, false><<<dim3(1, (Bn * Tp) / 128), 256>>>(
        Y2h, Y2l, Woph, Wopl, nullptr, Z2, 128, 128, 128, 128);

    // masked max over sequence
    k_maxred<<<dim3(Bn, 4), 128>>>(Z1, smask, Td, Td / 4, ob1);
    k_maxred<<<dim3(Bn, 16), 128>>>(Z2, pmask, Tp, Tp / 16, ob2);

    // decode + add output bias
    k_out<<<(Bn * 128 + 255) / 256, 256>>>(ob1, ob2, bpd, bpp, out);
}